// round 10
// baseline (speedup 1.0000x reference)
#include <cuda_runtime.h>
#include <cuda_fp16.h>
#include <cstdint>

// Fused int4-dequant + GEMM via mma.sync.m16n8k16 f32-acc (base ISA; tcgen05
// unavailable through the harness's compute_103 PTX path).
// R10: 4 warps x (64x64) warp tiles at 128 threads/CTA, 2 CTA/SM. Cuts A-frag
// replication 4->2 (smem reads 96->64KB/CTA-stage), dropping crossbar below
// the tensor-pipe floor (R9 profile: crossbar and tensor exactly co-saturated).

#define MM   8192
#define NN   4096
#define KK   4096
#define NGRP 32
#define KW   512

#define BM 128
#define BN 128
#define BK 64
#define NSTG 3
#define PITCH 72                        // halfs per row: 128B data + 16B pad
#define TILE_HALFS (128 * PITCH)        // 9216 halfs = 18432 B
#define STAGE_HALFS (2 * TILE_HALFS)    // A + B
#define SMEM_BYTES (NSTG * STAGE_HALFS * 2)   // 110592
#define NKITER (KK / BK)                // 64

// ---------------- device scratch ----------------
__device__ __half g_xh[(size_t)MM * KK];
__device__ __half g_wh[(size_t)NN * KK];

__device__ __forceinline__ uint32_t smem_u32(const void* p) {
    return (uint32_t)__cvta_generic_to_shared(p);
}

#define LDSM_X4(r, addr) \
    asm volatile("ldmatrix.sync.aligned.m8n8.x4.shared.b16 {%0,%1,%2,%3}, [%4];" \
                 : "=r"((r)[0]), "=r"((r)[1]), "=r"((r)[2]), "=r"((r)[3]) \
                 : "r"(addr))

#define MMA16816(c, a, b0, b1) \
    asm volatile("mma.sync.aligned.m16n8k16.row.col.f32.f16.f16.f32 " \
                 "{%0,%1,%2,%3}, {%4,%5,%6,%7}, {%8,%9}, {%0,%1,%2,%3};" \
                 : "+f"((c)[0]), "+f"((c)[1]), "+f"((c)[2]), "+f"((c)[3]) \
                 : "r"((a)[0]), "r"((a)[1]), "r"((a)[2]), "r"((a)[3]), \
                   "r"(b0), "r"(b1))

#define CP16(dst, src) \
    asm volatile("cp.async.cg.shared.global [%0], [%1], 16;" :: "r"(dst), "l"(src))

// ---------------- fused prep: round x + dequant W ----------------
#define XBLOCKS 16384                   // MM*KK / 2048
__global__ void __launch_bounds__(256) prep_kernel(const float* __restrict__ x,
                                                   const int* __restrict__ qw,
                                                   const float* __restrict__ sc,
                                                   const float* __restrict__ zp) {
    if (blockIdx.x < XBLOCKS) {
        size_t i = ((size_t)blockIdx.x * 256 + threadIdx.x) * 8;
        float4 v0 = *(const float4*)(x + i);
        float4 v1 = *(const float4*)(x + i + 4);
        float f[8] = {v0.x, v0.y, v0.z, v0.w, v1.x, v1.y, v1.z, v1.w};
        __half h[8];
#pragma unroll
        for (int j = 0; j < 8; j++) h[j] = __float2half_rn(f[j]);
        *(uint4*)(g_xh + i) = *(const uint4*)h;
    } else {
        int idx = (blockIdx.x - XBLOCKS) * 256 + threadIdx.x;   // word index
        int n = idx >> 9;
        int w = idx & 511;
        unsigned word = ((const unsigned*)qw)[idx];
        int g = w >> 4;
        float s = sc[n * NGRP + g];
        float z = zp[n * NGRP + g];
        __half o[8];
#pragma unroll
        for (int i = 0; i < 8; i++) {
            float q = (float)((word >> (4 * i)) & 0xF);
            o[i] = __float2half_rn(s * (q - z));
        }
        *(uint4*)(g_wh + (size_t)n * KK + w * 8) = *(const uint4*)o;
    }
}

// ---------------- GEMM: 128 threads, 4 warps of 64x64 ----------------
__global__ void __launch_bounds__(128, 2)
gemm_fp16_kernel(const float* __restrict__ bias, float* __restrict__ out) {
    extern __shared__ __half sm[];
    const int tid = threadIdx.x;
    const int wid = tid >> 5;
    const int lane = tid & 31;
    const int warp_m = wid >> 1;       // 0..1 -> 64 rows
    const int warp_n = wid & 1;        // 0..1 -> 64 cols
    const int m0 = blockIdx.y * BM;
    const int n0 = blockIdx.x * BN;

    float acc[4][8][4];
#pragma unroll
    for (int i = 0; i < 4; i++)
#pragma unroll
        for (int j = 0; j < 8; j++)
#pragma unroll
            for (int r = 0; r < 4; r++) acc[i][j][r] = 0.f;

    const int lrow = tid >> 3;         // 0..15
    const int lc = tid & 7;            // 0..7

    auto load_stage = [&](int s) {
        int buf = s % NSTG;
        uint32_t st = smem_u32(sm + buf * STAGE_HALFS);
        int k0 = s * BK;
        const __half* Ah = g_xh + (size_t)m0 * KK + k0;
        const __half* Bh = g_wh + (size_t)n0 * KK + k0;
#pragma unroll
        for (int i = 0; i < 8; i++) {
            int row = lrow + i * 16;
            uint32_t doff = (uint32_t)(row * PITCH + lc * 8) * 2;
            size_t soff = (size_t)row * KK + lc * 8;
            CP16(st + doff, Ah + soff);
            CP16(st + TILE_HALFS * 2 + doff, Bh + soff);
        }
        asm volatile("cp.async.commit_group;");
    };

    load_stage(0);
    load_stage(1);

    const int lrow16 = lane & 15;
    const int lk16 = (lane >> 4) * 16;  // byte offset of 8-half group

    const uint32_t a_ro = (uint32_t)((warp_m * 64 + lrow16) * PITCH) * 2 + lk16;
    const uint32_t b_ro = (uint32_t)((warp_n * 64 + lrow16) * PITCH) * 2 + lk16;

    uint32_t ah[2][4][4], bb[2][4][4];

    for (int s = 0; s < NKITER; s++) {
        if (s + 1 < NKITER)
            asm volatile("cp.async.wait_group 1;" ::: "memory");
        else
            asm volatile("cp.async.wait_group 0;" ::: "memory");
        __syncthreads();

        int buf = s % NSTG;
        uint32_t sA = smem_u32(sm + buf * STAGE_HALFS);
        uint32_t sB = sA + TILE_HALFS * 2;

        // preload ks=0 fragments into buffer 0
#pragma unroll
        for (int mi = 0; mi < 4; mi++)
            LDSM_X4(ah[0][mi], sA + a_ro + (uint32_t)(mi * 16 * PITCH) * 2);
#pragma unroll
        for (int ng = 0; ng < 4; ng++)
            LDSM_X4(bb[0][ng], sB + b_ro + (uint32_t)(ng * 16 * PITCH) * 2);

        if (s + 2 < NKITER) load_stage(s + 2);

#pragma unroll
        for (int ks = 0; ks < 4; ks++) {
            const int cur = ks & 1;
            const int nxt = cur ^ 1;
            if (ks < 3) {
                uint32_t kb = (uint32_t)((ks + 1) * 32);
#pragma unroll
                for (int mi = 0; mi < 4; mi++)
                    LDSM_X4(ah[nxt][mi], sA + a_ro + (uint32_t)(mi * 16 * PITCH) * 2 + kb);
#pragma unroll
                for (int ng = 0; ng < 4; ng++)
                    LDSM_X4(bb[nxt][ng], sB + b_ro + (uint32_t)(ng * 16 * PITCH) * 2 + kb);
            }
#pragma unroll
            for (int mi = 0; mi < 4; mi++) {
#pragma unroll
                for (int nj = 0; nj < 8; nj++) {
                    uint32_t b0 = bb[cur][nj >> 1][nj & 1];
                    uint32_t b1 = bb[cur][nj >> 1][(nj & 1) + 2];
                    MMA16816(acc[mi][nj], ah[cur][mi], b0, b1);
                }
            }
        }
    }

    // ---------------- epilogue ----------------
    const int rb = lane >> 2;
    const int cb = (lane & 3) * 2;
#pragma unroll
    for (int mi = 0; mi < 4; mi++) {
        int m = m0 + warp_m * 64 + mi * 16 + rb;
#pragma unroll
        for (int nj = 0; nj < 8; nj++) {
            int n = n0 + warp_n * 64 + nj * 8 + cb;
            float2 bv = *(const float2*)(bias + n);
            float2 o0, o1;
            o0.x = acc[mi][nj][0] + bv.x;
            o0.y = acc[mi][nj][1] + bv.y;
            o1.x = acc[mi][nj][2] + bv.x;
            o1.y = acc[mi][nj][3] + bv.y;
            *(float2*)(out + (size_t)m * NN + n) = o0;
            *(float2*)(out + (size_t)(m + 8) * NN + n) = o1;
        }
    }
}

// ---------------- launch ----------------
extern "C" void kernel_launch(void* const* d_in, const int* in_sizes, int n_in,
                              void* d_out, int out_size) {
    const float* x    = (const float*)d_in[0];
    const int*   qw   = (const int*)d_in[1];
    const float* sc   = (const float*)d_in[2];
    const float* zp   = (const float*)d_in[3];
    const float* bias = (const float*)d_in[4];
    float* out = (float*)d_out;

    cudaFuncSetAttribute(gemm_fp16_kernel,
                         cudaFuncAttributeMaxDynamicSharedMemorySize, SMEM_BYTES);

    prep_kernel<<<XBLOCKS + (NN * KW) / 256, 256>>>(x, qw, sc, zp);
    gemm_fp16_kernel<<<dim3(NN / BN, MM / BM), 128, SMEM_BYTES>>>(bias, out);
}

// round 11
// speedup vs baseline: 1.0832x; 1.0832x over previous
#include <cuda_runtime.h>
#include <cuda_fp16.h>
#include <cstdint>

// Fused int4-dequant + GEMM via mma.sync.m16n8k16 f32-acc (base ISA; tcgen05
// unavailable through the harness's compute_103 PTX path).
// R11: R9 structure with a compile-time-specialized main loop — outer loop
// unrolled x3 so smem buffer bases are constants, gmem srcs are running
// pointers, wait_group immediates specialized. Goal: strip the ALU/issue
// overhead (alu was 17.9%) that stretches the HMMA dispatch interval.

#define MM   8192
#define NN   4096
#define KK   4096
#define NGRP 32
#define KW   512

#define BM 128
#define BN 128
#define BK 64
#define NSTG 3
#define PITCH 72                        // halfs per row: 128B data + 16B pad
#define TILE_HALFS (128 * PITCH)        // 9216 halfs = 18432 B
#define STAGE_HALFS (2 * TILE_HALFS)    // A + B
#define SMEM_BYTES (NSTG * STAGE_HALFS * 2)   // 110592
#define NKITER (KK / BK)                // 64

// ---------------- device scratch ----------------
__device__ __half g_xh[(size_t)MM * KK];
__device__ __half g_wh[(size_t)NN * KK];

__device__ __forceinline__ uint32_t smem_u32(const void* p) {
    return (uint32_t)__cvta_generic_to_shared(p);
}

#define LDSM_X4(r, addr) \
    asm volatile("ldmatrix.sync.aligned.m8n8.x4.shared.b16 {%0,%1,%2,%3}, [%4];" \
                 : "=r"((r)[0]), "=r"((r)[1]), "=r"((r)[2]), "=r"((r)[3]) \
                 : "r"(addr))

#define MMA16816(c, a, b0, b1) \
    asm volatile("mma.sync.aligned.m16n8k16.row.col.f32.f16.f16.f32 " \
                 "{%0,%1,%2,%3}, {%4,%5,%6,%7}, {%8,%9}, {%0,%1,%2,%3};" \
                 : "+f"((c)[0]), "+f"((c)[1]), "+f"((c)[2]), "+f"((c)[3]) \
                 : "r"((a)[0]), "r"((a)[1]), "r"((a)[2]), "r"((a)[3]), \
                   "r"(b0), "r"(b1))

#define CP16(dst, src) \
    asm volatile("cp.async.cg.shared.global [%0], [%1], 16;" :: "r"(dst), "l"(src))

// ---------------- fused prep: round x + dequant W ----------------
#define XBLOCKS 16384                   // MM*KK / 2048
__global__ void __launch_bounds__(256) prep_kernel(const float* __restrict__ x,
                                                   const int* __restrict__ qw,
                                                   const float* __restrict__ sc,
                                                   const float* __restrict__ zp) {
    if (blockIdx.x < XBLOCKS) {
        size_t i = ((size_t)blockIdx.x * 256 + threadIdx.x) * 8;
        float4 v0 = *(const float4*)(x + i);
        float4 v1 = *(const float4*)(x + i + 4);
        float f[8] = {v0.x, v0.y, v0.z, v0.w, v1.x, v1.y, v1.z, v1.w};
        __half h[8];
#pragma unroll
        for (int j = 0; j < 8; j++) h[j] = __float2half_rn(f[j]);
        *(uint4*)(g_xh + i) = *(const uint4*)h;
    } else {
        int idx = (blockIdx.x - XBLOCKS) * 256 + threadIdx.x;   // word index
        int n = idx >> 9;
        int w = idx & 511;
        unsigned word = ((const unsigned*)qw)[idx];
        int g = w >> 4;
        float s = sc[n * NGRP + g];
        float z = zp[n * NGRP + g];
        __half o[8];
#pragma unroll
        for (int i = 0; i < 8; i++) {
            float q = (float)((word >> (4 * i)) & 0xF);
            o[i] = __float2half_rn(s * (q - z));
        }
        *(uint4*)(g_wh + (size_t)n * KK + w * 8) = *(const uint4*)o;
    }
}

// ---------------- GEMM ----------------
__global__ void __launch_bounds__(256, 2)
gemm_fp16_kernel(const float* __restrict__ bias, float* __restrict__ out) {
    extern __shared__ __half sm[];
    const int tid = threadIdx.x;
    const int wid = tid >> 5;
    const int lane = tid & 31;
    const int warp_m = wid >> 2;       // 0..1 -> 64 rows each
    const int warp_n = wid & 3;        // 0..3 -> 32 cols each
    const int m0 = blockIdx.y * BM;
    const int n0 = blockIdx.x * BN;

    float acc[4][4][4];
#pragma unroll
    for (int i = 0; i < 4; i++)
#pragma unroll
        for (int j = 0; j < 4; j++)
#pragma unroll
            for (int r = 0; r < 4; r++) acc[i][j][r] = 0.f;

    // ---- loader constants (per thread) ----
    const int lrow = tid >> 3;         // 0..31
    const int lc = tid & 7;            // 0..7
    const uint32_t woff = (uint32_t)(lrow * PITCH + lc * 8) * 2;  // write offset in tile
    // running gmem pointers (advance BK halfs per issued stage)
    const __half* gA = g_xh + (size_t)(m0 + lrow) * KK + lc * 8;
    const __half* gB = g_wh + (size_t)(n0 + lrow) * KK + lc * 8;

    // per-buffer smem bases (compile-time-selected in the bodies)
    const uint32_t sbase = smem_u32(sm);
    const uint32_t stA0 = sbase;
    const uint32_t stA1 = sbase + STAGE_HALFS * 2;
    const uint32_t stA2 = sbase + STAGE_HALFS * 4;

    // issue one stage of cp.async into buffer base wb; advances gA/gB
#define LOAD_STAGE(wb)                                                        \
    do {                                                                      \
        _Pragma("unroll")                                                     \
        for (int i_ = 0; i_ < 4; i_++) {                                      \
            uint32_t d_ = (wb) + woff + (uint32_t)(i_ * 32 * PITCH * 2);      \
            CP16(d_, gA + (size_t)(i_ * 32) * KK);                            \
            CP16(d_ + TILE_HALFS * 2, gB + (size_t)(i_ * 32) * KK);           \
        }                                                                     \
        asm volatile("cp.async.commit_group;");                               \
        gA += BK;                                                             \
        gB += BK;                                                             \
    } while (0)

    LOAD_STAGE(stA0);
    LOAD_STAGE(stA1);

    const int lrow16 = lane & 15;
    const int lk16 = (lane >> 4) * 16;  // byte offset of 8-half group
    const uint32_t a_ro = (uint32_t)((warp_m * 64 + lrow16) * PITCH) * 2 + lk16;
    const uint32_t b_ro = (uint32_t)((warp_n * 32 + lrow16) * PITCH) * 2 + lk16 + TILE_HALFS * 2;

    uint32_t ah[2][4][4], bb[2][2][4];

    // One stage body. curb/nxtb are compile-time buffer bases; do_load is a
    // compile-time or cheap-runtime predicate; WAITN is the wait immediate.
#define STAGE_BODY(curb, nxtb, do_load, waitn)                                \
    do {                                                                      \
        asm volatile("cp.async.wait_group " #waitn ";" ::: "memory");         \
        __syncthreads();                                                      \
        const uint32_t sA_ = (curb) + a_ro;                                   \
        const uint32_t sB_ = (curb) + b_ro;                                   \
        _Pragma("unroll")                                                     \
        for (int mi_ = 0; mi_ < 4; mi_++)                                     \
            LDSM_X4(ah[0][mi_], sA_ + (uint32_t)(mi_ * 16 * PITCH * 2));      \
        _Pragma("unroll")                                                     \
        for (int ng_ = 0; ng_ < 2; ng_++)                                     \
            LDSM_X4(bb[0][ng_], sB_ + (uint32_t)(ng_ * 16 * PITCH * 2));      \
        if (do_load) LOAD_STAGE(nxtb);                                        \
        _Pragma("unroll")                                                     \
        for (int ks_ = 0; ks_ < 4; ks_++) {                                   \
            const int cur_ = ks_ & 1;                                         \
            const int nxt_ = cur_ ^ 1;                                        \
            if (ks_ < 3) {                                                    \
                const uint32_t kb_ = (uint32_t)((ks_ + 1) * 32);              \
                _Pragma("unroll")                                             \
                for (int mi_ = 0; mi_ < 4; mi_++)                             \
                    LDSM_X4(ah[nxt_][mi_],                                    \
                            sA_ + (uint32_t)(mi_ * 16 * PITCH * 2) + kb_);    \
                _Pragma("unroll")                                             \
                for (int ng_ = 0; ng_ < 2; ng_++)                             \
                    LDSM_X4(bb[nxt_][ng_],                                    \
                            sB_ + (uint32_t)(ng_ * 16 * PITCH * 2) + kb_);    \
            }                                                                 \
            _Pragma("unroll")                                                 \
            for (int mi_ = 0; mi_ < 4; mi_++) {                               \
                _Pragma("unroll")                                             \
                for (int nj_ = 0; nj_ < 4; nj_++) {                           \
                    uint32_t b0_ = bb[cur_][nj_ >> 1][nj_ & 1];               \
                    uint32_t b1_ = bb[cur_][nj_ >> 1][(nj_ & 1) + 2];         \
                    MMA16816(acc[mi_][nj_], ah[cur_][mi_], b0_, b1_);         \
                }                                                             \
            }                                                                 \
        }                                                                     \
    } while (0)

    // stages 0..62 in 21 triples (buf = s % 3 is compile-time per body);
    // stage s loads stage s+2 into buffer (s+2)%3. Only s=62 skips the load.
    for (int t = 0; t < 21; t++) {
        STAGE_BODY(stA0, stA2, true, 1);            // s = 3t
        STAGE_BODY(stA1, stA0, true, 1);            // s = 3t+1
        STAGE_BODY(stA2, stA1, (t < 20), 1);        // s = 3t+2 (s=62 skips)
    }
    STAGE_BODY(stA0, stA1, false, 0);               // s = 63 (63%3 == 0)

    // ---------------- epilogue ----------------
    const int rb = lane >> 2;
    const int cb = (lane & 3) * 2;
#pragma unroll
    for (int mi = 0; mi < 4; mi++) {
        int m = m0 + warp_m * 64 + mi * 16 + rb;
#pragma unroll
        for (int nj = 0; nj < 4; nj++) {
            int n = n0 + warp_n * 32 + nj * 8 + cb;
            float2 bv = *(const float2*)(bias + n);
            float2 o0, o1;
            o0.x = acc[mi][nj][0] + bv.x;
            o0.y = acc[mi][nj][1] + bv.y;
            o1.x = acc[mi][nj][2] + bv.x;
            o1.y = acc[mi][nj][3] + bv.y;
            *(float2*)(out + (size_t)m * NN + n) = o0;
            *(float2*)(out + (size_t)(m + 8) * NN + n) = o1;
        }
    }
}

// ---------------- launch ----------------
extern "C" void kernel_launch(void* const* d_in, const int* in_sizes, int n_in,
                              void* d_out, int out_size) {
    const float* x    = (const float*)d_in[0];
    const int*   qw   = (const int*)d_in[1];
    const float* sc   = (const float*)d_in[2];
    const float* zp   = (const float*)d_in[3];
    const float* bias = (const float*)d_in[4];
    float* out = (float*)d_out;

    cudaFuncSetAttribute(gemm_fp16_kernel,
                         cudaFuncAttributeMaxDynamicSharedMemorySize, SMEM_BYTES);

    prep_kernel<<<XBLOCKS + (NN * KW) / 256, 256>>>(x, qw, sc, zp);
    gemm_fp16_kernel<<<dim3(NN / BN, MM / BM), 256, SMEM_BYTES>>>(bias, out);
}

// round 12
// speedup vs baseline: 1.2218x; 1.1280x over previous
#include <cuda_runtime.h>
#include <cuda_fp16.h>
#include <cstdint>

// Fused int4-dequant + GEMM via mma.sync.m16n8k16 f32-acc (base ISA; tcgen05
// unavailable through the harness's compute_103 PTX path).
// R12: R11 + fine-grained interleaving — LDSM prefetches and cp.async pieces
// are distributed one-or-two per 4-MMA group (asm volatile order is preserved
// by ptxas, so bursts starve the tensor pipe; spreading them keeps an HMMA
// always eligible).

#define MM   8192
#define NN   4096
#define KK   4096
#define NGRP 32
#define KW   512

#define BM 128
#define BN 128
#define BK 64
#define NSTG 3
#define PITCH 72                        // halfs per row: 128B data + 16B pad
#define TILE_HALFS (128 * PITCH)        // 9216 halfs = 18432 B
#define STAGE_HALFS (2 * TILE_HALFS)    // A + B
#define SMEM_BYTES (NSTG * STAGE_HALFS * 2)   // 110592
#define NKITER (KK / BK)                // 64

// ---------------- device scratch ----------------
__device__ __half g_xh[(size_t)MM * KK];
__device__ __half g_wh[(size_t)NN * KK];

__device__ __forceinline__ uint32_t smem_u32(const void* p) {
    return (uint32_t)__cvta_generic_to_shared(p);
}

#define LDSM_X4(r, addr) \
    asm volatile("ldmatrix.sync.aligned.m8n8.x4.shared.b16 {%0,%1,%2,%3}, [%4];" \
                 : "=r"((r)[0]), "=r"((r)[1]), "=r"((r)[2]), "=r"((r)[3]) \
                 : "r"(addr))

#define MMA16816(c, a, b0, b1) \
    asm volatile("mma.sync.aligned.m16n8k16.row.col.f32.f16.f16.f32 " \
                 "{%0,%1,%2,%3}, {%4,%5,%6,%7}, {%8,%9}, {%0,%1,%2,%3};" \
                 : "+f"((c)[0]), "+f"((c)[1]), "+f"((c)[2]), "+f"((c)[3]) \
                 : "r"((a)[0]), "r"((a)[1]), "r"((a)[2]), "r"((a)[3]), \
                   "r"(b0), "r"(b1))

#define CP16(dst, src) \
    asm volatile("cp.async.cg.shared.global [%0], [%1], 16;" :: "r"(dst), "l"(src))

// ---------------- fused prep: round x + dequant W ----------------
#define XBLOCKS 16384                   // MM*KK / 2048
__global__ void __launch_bounds__(256) prep_kernel(const float* __restrict__ x,
                                                   const int* __restrict__ qw,
                                                   const float* __restrict__ sc,
                                                   const float* __restrict__ zp) {
    if (blockIdx.x < XBLOCKS) {
        size_t i = ((size_t)blockIdx.x * 256 + threadIdx.x) * 8;
        float4 v0 = *(const float4*)(x + i);
        float4 v1 = *(const float4*)(x + i + 4);
        float f[8] = {v0.x, v0.y, v0.z, v0.w, v1.x, v1.y, v1.z, v1.w};
        __half h[8];
#pragma unroll
        for (int j = 0; j < 8; j++) h[j] = __float2half_rn(f[j]);
        *(uint4*)(g_xh + i) = *(const uint4*)h;
    } else {
        int idx = (blockIdx.x - XBLOCKS) * 256 + threadIdx.x;   // word index
        int n = idx >> 9;
        int w = idx & 511;
        unsigned word = ((const unsigned*)qw)[idx];
        int g = w >> 4;
        float s = sc[n * NGRP + g];
        float z = zp[n * NGRP + g];
        __half o[8];
#pragma unroll
        for (int i = 0; i < 8; i++) {
            float q = (float)((word >> (4 * i)) & 0xF);
            o[i] = __float2half_rn(s * (q - z));
        }
        *(uint4*)(g_wh + (size_t)n * KK + w * 8) = *(const uint4*)o;
    }
}

// ---------------- GEMM ----------------
__global__ void __launch_bounds__(256, 2)
gemm_fp16_kernel(const float* __restrict__ bias, float* __restrict__ out) {
    extern __shared__ __half sm[];
    const int tid = threadIdx.x;
    const int wid = tid >> 5;
    const int lane = tid & 31;
    const int warp_m = wid >> 2;       // 0..1 -> 64 rows each
    const int warp_n = wid & 3;        // 0..3 -> 32 cols each
    const int m0 = blockIdx.y * BM;
    const int n0 = blockIdx.x * BN;

    float acc[4][4][4];
#pragma unroll
    for (int i = 0; i < 4; i++)
#pragma unroll
        for (int j = 0; j < 4; j++)
#pragma unroll
            for (int r = 0; r < 4; r++) acc[i][j][r] = 0.f;

    // ---- loader constants (per thread) ----
    const int lrow = tid >> 3;         // 0..31
    const int lc = tid & 7;            // 0..7
    const uint32_t woff = (uint32_t)(lrow * PITCH + lc * 8) * 2;
    const __half* gA = g_xh + (size_t)(m0 + lrow) * KK + lc * 8;
    const __half* gB = g_wh + (size_t)(n0 + lrow) * KK + lc * 8;

    const uint32_t sbase = smem_u32(sm);
    const uint32_t stA0 = sbase;
    const uint32_t stA1 = sbase + STAGE_HALFS * 2;
    const uint32_t stA2 = sbase + STAGE_HALFS * 4;

    // one 2-cp.async piece (row blocks 2i and 2i+1 of 4... actually block i of 4)
#define LOAD_PIECE(wb, i_)                                                    \
    do {                                                                      \
        uint32_t d_ = (wb) + woff + (uint32_t)(i_ * 32 * PITCH * 2);          \
        CP16(d_, gA + (size_t)(i_ * 32) * KK);                                \
        CP16(d_ + TILE_HALFS * 2, gB + (size_t)(i_ * 32) * KK);               \
    } while (0)

#define LOAD_STAGE_FULL(wb)                                                   \
    do {                                                                      \
        LOAD_PIECE(wb, 0); LOAD_PIECE(wb, 1);                                 \
        LOAD_PIECE(wb, 2); LOAD_PIECE(wb, 3);                                 \
        asm volatile("cp.async.commit_group;");                               \
        gA += BK; gB += BK;                                                   \
    } while (0)

    LOAD_STAGE_FULL(stA0);
    LOAD_STAGE_FULL(stA1);

    const int lrow16 = lane & 15;
    const int lk16 = (lane >> 4) * 16;
    const uint32_t a_ro = (uint32_t)((warp_m * 64 + lrow16) * PITCH) * 2 + lk16;
    const uint32_t b_ro = (uint32_t)((warp_n * 32 + lrow16) * PITCH) * 2 + lk16 + TILE_HALFS * 2;

    uint32_t ah[2][4][4], bb[2][2][4];

    // 4 MMAs of one (cur, mi) group
#define MMA_GROUP(cur_, mi_)                                                  \
    do {                                                                      \
        _Pragma("unroll")                                                     \
        for (int nj_ = 0; nj_ < 4; nj_++) {                                   \
            uint32_t b0_ = bb[cur_][nj_ >> 1][nj_ & 1];                       \
            uint32_t b1_ = bb[cur_][nj_ >> 1][(nj_ & 1) + 2];                 \
            MMA16816(acc[mi_][nj_], ah[cur_][mi_], b0_, b1_);                 \
        }                                                                     \
    } while (0)

    // One stage. Memory ops distributed: per ks<3, group mi issues
    // LDSM ah[nxt][mi] (+ bb[nxt][0/1] on mi=0/1); cp piece at (ks, mi==2).
#define STAGE_BODY(curb, nxtb, do_load, waitn)                                \
    do {                                                                      \
        asm volatile("cp.async.wait_group " #waitn ";" ::: "memory");         \
        __syncthreads();                                                      \
        const uint32_t sA_ = (curb) + a_ro;                                   \
        const uint32_t sB_ = (curb) + b_ro;                                   \
        _Pragma("unroll")                                                     \
        for (int mi_ = 0; mi_ < 4; mi_++)                                     \
            LDSM_X4(ah[0][mi_], sA_ + (uint32_t)(mi_ * 16 * PITCH * 2));      \
        _Pragma("unroll")                                                     \
        for (int ng_ = 0; ng_ < 2; ng_++)                                     \
            LDSM_X4(bb[0][ng_], sB_ + (uint32_t)(ng_ * 16 * PITCH * 2));      \
        _Pragma("unroll")                                                     \
        for (int ks_ = 0; ks_ < 4; ks_++) {                                   \
            const int cur_ = ks_ & 1;                                         \
            const int nxt_ = cur_ ^ 1;                                        \
            const uint32_t kb_ = (uint32_t)((ks_ + 1) * 32);                  \
            /* mi = 0 */                                                      \
            if (ks_ < 3) {                                                    \
                LDSM_X4(ah[nxt_][0], sA_ + kb_);                              \
                LDSM_X4(bb[nxt_][0], sB_ + kb_);                              \
            }                                                                 \
            MMA_GROUP(cur_, 0);                                               \
            /* mi = 1 */                                                      \
            if (ks_ < 3) {                                                    \
                LDSM_X4(ah[nxt_][1], sA_ + (uint32_t)(16 * PITCH * 2) + kb_); \
                LDSM_X4(bb[nxt_][1], sB_ + (uint32_t)(16 * PITCH * 2) + kb_); \
            }                                                                 \
            MMA_GROUP(cur_, 1);                                               \
            /* mi = 2 (+ cp piece) */                                         \
            if (ks_ < 3)                                                      \
                LDSM_X4(ah[nxt_][2], sA_ + (uint32_t)(32 * PITCH * 2) + kb_); \
            if (do_load) LOAD_PIECE(nxtb, ks_);                               \
            MMA_GROUP(cur_, 2);                                               \
            /* mi = 3 */                                                      \
            if (ks_ < 3)                                                      \
                LDSM_X4(ah[nxt_][3], sA_ + (uint32_t)(48 * PITCH * 2) + kb_); \
            MMA_GROUP(cur_, 3);                                               \
        }                                                                     \
        if (do_load) {                                                        \
            asm volatile("cp.async.commit_group;");                           \
            gA += BK; gB += BK;                                               \
        }                                                                     \
    } while (0)

    // stages 0..62 in 21 triples; stage s loads s+2 into (s+2)%3.
    for (int t = 0; t < 21; t++) {
        STAGE_BODY(stA0, stA2, true, 1);            // s = 3t
        STAGE_BODY(stA1, stA0, true, 1);            // s = 3t+1
        STAGE_BODY(stA2, stA1, (t < 20), 1);        // s = 3t+2 (s=62 skips)
    }
    STAGE_BODY(stA0, stA1, false, 0);               // s = 63

    // ---------------- epilogue ----------------
    const int rb = lane >> 2;
    const int cb = (lane & 3) * 2;
#pragma unroll
    for (int mi = 0; mi < 4; mi++) {
        int m = m0 + warp_m * 64 + mi * 16 + rb;
#pragma unroll
        for (int nj = 0; nj < 4; nj++) {
            int n = n0 + warp_n * 32 + nj * 8 + cb;
            float2 bv = *(const float2*)(bias + n);
            float2 o0, o1;
            o0.x = acc[mi][nj][0] + bv.x;
            o0.y = acc[mi][nj][1] + bv.y;
            o1.x = acc[mi][nj][2] + bv.x;
            o1.y = acc[mi][nj][3] + bv.y;
            *(float2*)(out + (size_t)m * NN + n) = o0;
            *(float2*)(out + (size_t)(m + 8) * NN + n) = o1;
        }
    }
}

// ---------------- launch ----------------
extern "C" void kernel_launch(void* const* d_in, const int* in_sizes, int n_in,
                              void* d_out, int out_size) {
    const float* x    = (const float*)d_in[0];
    const int*   qw   = (const int*)d_in[1];
    const float* sc   = (const float*)d_in[2];
    const float* zp   = (const float*)d_in[3];
    const float* bias = (const float*)d_in[4];
    float* out = (float*)d_out;

    cudaFuncSetAttribute(gemm_fp16_kernel,
                         cudaFuncAttributeMaxDynamicSharedMemorySize, SMEM_BYTES);

    prep_kernel<<<XBLOCKS + (NN * KW) / 256, 256>>>(x, qw, sc, zp);
    gemm_fp16_kernel<<<dim3(NN / BN, MM / BM), 256, SMEM_BYTES>>>(bias, out);
}

// round 13
// speedup vs baseline: 1.4094x; 1.1536x over previous
#include <cuda_runtime.h>
#include <cuda_fp16.h>
#include <cstdint>

// Fused int4-dequant + GEMM via mma.sync.m16n8k16 f32-acc (base ISA; tcgen05
// unavailable through the harness's compute_103 PTX path).
// R13: R12 + cross-stage fragment prefetch. The per-stage barrier moves to the
// ks=2/ks=3 boundary (all reads of the current buffer are done by then), and
// ks=3's MMA groups prefetch the NEXT stage's ks=0 fragments from the already-
// resident next buffer — eliminating the post-barrier 6-LDSM head burst that
// drained the tensor pipe once per stage.

#define MM   8192
#define NN   4096
#define KK   4096
#define NGRP 32
#define KW   512

#define BM 128
#define BN 128
#define BK 64
#define NSTG 3
#define PITCH 72                        // halfs per row: 128B data + 16B pad
#define TILE_HALFS (128 * PITCH)        // 9216 halfs = 18432 B
#define STAGE_HALFS (2 * TILE_HALFS)    // A + B
#define SMEM_BYTES (NSTG * STAGE_HALFS * 2)   // 110592
#define NKITER (KK / BK)                // 64

// ---------------- device scratch ----------------
__device__ __half g_xh[(size_t)MM * KK];
__device__ __half g_wh[(size_t)NN * KK];

__device__ __forceinline__ uint32_t smem_u32(const void* p) {
    return (uint32_t)__cvta_generic_to_shared(p);
}

#define LDSM_X4(r, addr) \
    asm volatile("ldmatrix.sync.aligned.m8n8.x4.shared.b16 {%0,%1,%2,%3}, [%4];" \
                 : "=r"((r)[0]), "=r"((r)[1]), "=r"((r)[2]), "=r"((r)[3]) \
                 : "r"(addr))

#define MMA16816(c, a, b0, b1) \
    asm volatile("mma.sync.aligned.m16n8k16.row.col.f32.f16.f16.f32 " \
                 "{%0,%1,%2,%3}, {%4,%5,%6,%7}, {%8,%9}, {%0,%1,%2,%3};" \
                 : "+f"((c)[0]), "+f"((c)[1]), "+f"((c)[2]), "+f"((c)[3]) \
                 : "r"((a)[0]), "r"((a)[1]), "r"((a)[2]), "r"((a)[3]), \
                   "r"(b0), "r"(b1))

#define CP16(dst, src) \
    asm volatile("cp.async.cg.shared.global [%0], [%1], 16;" :: "r"(dst), "l"(src))

// ---------------- fused prep: round x + dequant W ----------------
#define XBLOCKS 16384                   // MM*KK / 2048
__global__ void __launch_bounds__(256) prep_kernel(const float* __restrict__ x,
                                                   const int* __restrict__ qw,
                                                   const float* __restrict__ sc,
                                                   const float* __restrict__ zp) {
    if (blockIdx.x < XBLOCKS) {
        size_t i = ((size_t)blockIdx.x * 256 + threadIdx.x) * 8;
        float4 v0 = *(const float4*)(x + i);
        float4 v1 = *(const float4*)(x + i + 4);
        float f[8] = {v0.x, v0.y, v0.z, v0.w, v1.x, v1.y, v1.z, v1.w};
        __half h[8];
#pragma unroll
        for (int j = 0; j < 8; j++) h[j] = __float2half_rn(f[j]);
        *(uint4*)(g_xh + i) = *(const uint4*)h;
    } else {
        int idx = (blockIdx.x - XBLOCKS) * 256 + threadIdx.x;   // word index
        int n = idx >> 9;
        int w = idx & 511;
        unsigned word = ((const unsigned*)qw)[idx];
        int g = w >> 4;
        float s = sc[n * NGRP + g];
        float z = zp[n * NGRP + g];
        __half o[8];
#pragma unroll
        for (int i = 0; i < 8; i++) {
            float q = (float)((word >> (4 * i)) & 0xF);
            o[i] = __float2half_rn(s * (q - z));
        }
        *(uint4*)(g_wh + (size_t)n * KK + w * 8) = *(const uint4*)o;
    }
}

// ---------------- GEMM ----------------
__global__ void __launch_bounds__(256, 2)
gemm_fp16_kernel(const float* __restrict__ bias, float* __restrict__ out) {
    extern __shared__ __half sm[];
    const int tid = threadIdx.x;
    const int wid = tid >> 5;
    const int lane = tid & 31;
    const int warp_m = wid >> 2;       // 0..1 -> 64 rows each
    const int warp_n = wid & 3;        // 0..3 -> 32 cols each
    const int m0 = blockIdx.y * BM;
    const int n0 = blockIdx.x * BN;

    float acc[4][4][4];
#pragma unroll
    for (int i = 0; i < 4; i++)
#pragma unroll
        for (int j = 0; j < 4; j++)
#pragma unroll
            for (int r = 0; r < 4; r++) acc[i][j][r] = 0.f;

    // ---- loader constants (per thread) ----
    const int lrow = tid >> 3;         // 0..31
    const int lc = tid & 7;            // 0..7
    const uint32_t woff = (uint32_t)(lrow * PITCH + lc * 8) * 2;
    const __half* gA = g_xh + (size_t)(m0 + lrow) * KK + lc * 8;
    const __half* gB = g_wh + (size_t)(n0 + lrow) * KK + lc * 8;

    const uint32_t sbase = smem_u32(sm);
    const uint32_t stA0 = sbase;
    const uint32_t stA1 = sbase + STAGE_HALFS * 2;
    const uint32_t stA2 = sbase + STAGE_HALFS * 4;

#define LOAD_PIECE(wb, i_)                                                    \
    do {                                                                      \
        uint32_t d_ = (wb) + woff + (uint32_t)(i_ * 32 * PITCH * 2);          \
        CP16(d_, gA + (size_t)(i_ * 32) * KK);                                \
        CP16(d_ + TILE_HALFS * 2, gB + (size_t)(i_ * 32) * KK);               \
    } while (0)

#define LOAD_STAGE_FULL(wb)                                                   \
    do {                                                                      \
        LOAD_PIECE(wb, 0); LOAD_PIECE(wb, 1);                                 \
        LOAD_PIECE(wb, 2); LOAD_PIECE(wb, 3);                                 \
        asm volatile("cp.async.commit_group;");                               \
        gA += BK; gB += BK;                                                   \
    } while (0)

    LOAD_STAGE_FULL(stA0);
    LOAD_STAGE_FULL(stA1);

    const int lrow16 = lane & 15;
    const int lk16 = (lane >> 4) * 16;
    const uint32_t a_ro = (uint32_t)((warp_m * 64 + lrow16) * PITCH) * 2 + lk16;
    const uint32_t b_ro = (uint32_t)((warp_n * 32 + lrow16) * PITCH) * 2 + lk16 + TILE_HALFS * 2;

    uint32_t ah[2][4][4], bb[2][2][4];

#define MMA_GROUP(cur_, mi_)                                                  \
    do {                                                                      \
        _Pragma("unroll")                                                     \
        for (int nj_ = 0; nj_ < 4; nj_++) {                                   \
            uint32_t b0_ = bb[cur_][nj_ >> 1][nj_ & 1];                       \
            uint32_t b1_ = bb[cur_][nj_ >> 1][(nj_ & 1) + 2];                 \
            MMA16816(acc[mi_][nj_], ah[cur_][mi_], b0_, b1_);                 \
        }                                                                     \
    } while (0)

    // One stage. Entry invariant: this stage's ks=0 fragments are already in
    // ah[0]/bb[0] (prefetched by the previous stage's ks=3). ks=0..2 prefetch
    // ks+1 from curb; barrier sits after ks=2; ks=3 prefetches next stage's
    // ks=0 from nextb (resident by the wait). cp pieces for loadb distributed.
#define STAGE_BODY(curb, nextb, loadb, do_load, pf_next, waitn)               \
    do {                                                                      \
        const uint32_t sA_ = (curb) + a_ro;                                   \
        const uint32_t sB_ = (curb) + b_ro;                                   \
        _Pragma("unroll")                                                     \
        for (int ks_ = 0; ks_ < 3; ks_++) {                                   \
            const int cur_ = ks_ & 1;                                         \
            const int nxt_ = cur_ ^ 1;                                        \
            const uint32_t kb_ = (uint32_t)((ks_ + 1) * 32);                  \
            LDSM_X4(ah[nxt_][0], sA_ + kb_);                                  \
            LDSM_X4(bb[nxt_][0], sB_ + kb_);                                  \
            MMA_GROUP(cur_, 0);                                               \
            LDSM_X4(ah[nxt_][1], sA_ + (uint32_t)(16 * PITCH * 2) + kb_);     \
            LDSM_X4(bb[nxt_][1], sB_ + (uint32_t)(16 * PITCH * 2) + kb_);     \
            MMA_GROUP(cur_, 1);                                               \
            LDSM_X4(ah[nxt_][2], sA_ + (uint32_t)(32 * PITCH * 2) + kb_);     \
            if (do_load) LOAD_PIECE(loadb, ks_);                              \
            MMA_GROUP(cur_, 2);                                               \
            LDSM_X4(ah[nxt_][3], sA_ + (uint32_t)(48 * PITCH * 2) + kb_);     \
            MMA_GROUP(cur_, 3);                                               \
        }                                                                     \
        if (do_load) {                                                        \
            LOAD_PIECE(loadb, 3);                                             \
            asm volatile("cp.async.commit_group;");                           \
            gA += BK; gB += BK;                                               \
        }                                                                     \
        asm volatile("cp.async.wait_group " #waitn ";" ::: "memory");         \
        __syncthreads();                                                      \
        /* ks = 3 (cur=1): prefetch next stage's ks=0 into buffer 0 */        \
        if (pf_next) {                                                        \
            const uint32_t nA_ = (nextb) + a_ro;                              \
            const uint32_t nB_ = (nextb) + b_ro;                              \
            LDSM_X4(ah[0][0], nA_);                                           \
            LDSM_X4(bb[0][0], nB_);                                           \
            MMA_GROUP(1, 0);                                                  \
            LDSM_X4(ah[0][1], nA_ + (uint32_t)(16 * PITCH * 2));              \
            LDSM_X4(bb[0][1], nB_ + (uint32_t)(16 * PITCH * 2));              \
            MMA_GROUP(1, 1);                                                  \
            LDSM_X4(ah[0][2], nA_ + (uint32_t)(32 * PITCH * 2));              \
            MMA_GROUP(1, 2);                                                  \
            LDSM_X4(ah[0][3], nA_ + (uint32_t)(48 * PITCH * 2));              \
            MMA_GROUP(1, 3);                                                  \
        } else {                                                              \
            MMA_GROUP(1, 0); MMA_GROUP(1, 1);                                 \
            MMA_GROUP(1, 2); MMA_GROUP(1, 3);                                 \
        }                                                                     \
    } while (0)

    // prologue: stage 0's data is resident after wait; preload its ks=0 frags
    asm volatile("cp.async.wait_group 1;" ::: "memory");
    __syncthreads();
#pragma unroll
    for (int mi = 0; mi < 4; mi++)
        LDSM_X4(ah[0][mi], stA0 + a_ro + (uint32_t)(mi * 16 * PITCH * 2));
#pragma unroll
    for (int ng = 0; ng < 2; ng++)
        LDSM_X4(bb[0][ng], stA0 + b_ro + (uint32_t)(ng * 16 * PITCH * 2));

    // stages 0..59 in 20 triples; stage s reads s%3, prefetches (s+1)%3,
    // loads into (s+2)%3.
    for (int t = 0; t < 20; t++) {
        STAGE_BODY(stA0, stA1, stA2, true, true, 1);   // s = 3t
        STAGE_BODY(stA1, stA2, stA0, true, true, 1);   // s = 3t+1
        STAGE_BODY(stA2, stA0, stA1, true, true, 1);   // s = 3t+2
    }
    STAGE_BODY(stA0, stA1, stA2, true,  true, 1);      // s = 60
    STAGE_BODY(stA1, stA2, stA0, true,  true, 1);      // s = 61
    STAGE_BODY(stA2, stA0, stA1, false, true, 0);      // s = 62 (no load)
    STAGE_BODY(stA0, stA1, stA2, false, false, 0);     // s = 63 (final)

    // ---------------- epilogue ----------------
    const int rb = lane >> 2;
    const int cb = (lane & 3) * 2;
#pragma unroll
    for (int mi = 0; mi < 4; mi++) {
        int m = m0 + warp_m * 64 + mi * 16 + rb;
#pragma unroll
        for (int nj = 0; nj < 4; nj++) {
            int n = n0 + warp_n * 32 + nj * 8 + cb;
            float2 bv = *(const float2*)(bias + n);
            float2 o0, o1;
            o0.x = acc[mi][nj][0] + bv.x;
            o0.y = acc[mi][nj][1] + bv.y;
            o1.x = acc[mi][nj][2] + bv.x;
            o1.y = acc[mi][nj][3] + bv.y;
            *(float2*)(out + (size_t)m * NN + n) = o0;
            *(float2*)(out + (size_t)(m + 8) * NN + n) = o1;
        }
    }
}

// ---------------- launch ----------------
extern "C" void kernel_launch(void* const* d_in, const int* in_sizes, int n_in,
                              void* d_out, int out_size) {
    const float* x    = (const float*)d_in[0];
    const int*   qw   = (const int*)d_in[1];
    const float* sc   = (const float*)d_in[2];
    const float* zp   = (const float*)d_in[3];
    const float* bias = (const float*)d_in[4];
    float* out = (float*)d_out;

    cudaFuncSetAttribute(gemm_fp16_kernel,
                         cudaFuncAttributeMaxDynamicSharedMemorySize, SMEM_BYTES);

    prep_kernel<<<XBLOCKS + (NN * KW) / 256, 256>>>(x, qw, sc, zp);
    gemm_fp16_kernel<<<dim3(NN / BN, MM / BM), 256, SMEM_BYTES>>>(bias, out);
}

// round 14
// speedup vs baseline: 1.4306x; 1.0150x over previous
#include <cuda_runtime.h>
#include <cuda_fp16.h>
#include <cstdint>

// Fused int4-dequant + GEMM via mma.sync.m16n8k16 f32-acc (base ISA; tcgen05
// unavailable through the harness's compute_103 PTX path).
// R14: R13's schedule (distributed LDSM/cp.async, cross-stage fragment
// prefetch) on 64x64 warp tiles (4 warps, 128 threads, 2 CTA/SM). Cuts smem
// reads 96->64KB per CTA-stage (A and B replication both 2x), dropping the
// crossbar below the tensor-pipe demand (R13: both co-saturated at ~72-79%).

#define MM   8192
#define NN   4096
#define KK   4096
#define NGRP 32
#define KW   512

#define BM 128
#define BN 128
#define BK 64
#define NSTG 3
#define PITCH 72                        // halfs per row: 128B data + 16B pad
#define TILE_HALFS (128 * PITCH)        // 9216 halfs = 18432 B
#define STAGE_HALFS (2 * TILE_HALFS)    // A + B
#define SMEM_BYTES (NSTG * STAGE_HALFS * 2)   // 110592
#define NKITER (KK / BK)                // 64

// ---------------- device scratch ----------------
__device__ __half g_xh[(size_t)MM * KK];
__device__ __half g_wh[(size_t)NN * KK];

__device__ __forceinline__ uint32_t smem_u32(const void* p) {
    return (uint32_t)__cvta_generic_to_shared(p);
}

#define LDSM_X4(r, addr) \
    asm volatile("ldmatrix.sync.aligned.m8n8.x4.shared.b16 {%0,%1,%2,%3}, [%4];" \
                 : "=r"((r)[0]), "=r"((r)[1]), "=r"((r)[2]), "=r"((r)[3]) \
                 : "r"(addr))

#define MMA16816(c, a, b0, b1) \
    asm volatile("mma.sync.aligned.m16n8k16.row.col.f32.f16.f16.f32 " \
                 "{%0,%1,%2,%3}, {%4,%5,%6,%7}, {%8,%9}, {%0,%1,%2,%3};" \
                 : "+f"((c)[0]), "+f"((c)[1]), "+f"((c)[2]), "+f"((c)[3]) \
                 : "r"((a)[0]), "r"((a)[1]), "r"((a)[2]), "r"((a)[3]), \
                   "r"(b0), "r"(b1))

#define CP16(dst, src) \
    asm volatile("cp.async.cg.shared.global [%0], [%1], 16;" :: "r"(dst), "l"(src))

// ---------------- fused prep: round x + dequant W ----------------
#define XBLOCKS 16384                   // MM*KK / 2048
__global__ void __launch_bounds__(256) prep_kernel(const float* __restrict__ x,
                                                   const int* __restrict__ qw,
                                                   const float* __restrict__ sc,
                                                   const float* __restrict__ zp) {
    if (blockIdx.x < XBLOCKS) {
        size_t i = ((size_t)blockIdx.x * 256 + threadIdx.x) * 8;
        float4 v0 = *(const float4*)(x + i);
        float4 v1 = *(const float4*)(x + i + 4);
        float f[8] = {v0.x, v0.y, v0.z, v0.w, v1.x, v1.y, v1.z, v1.w};
        __half h[8];
#pragma unroll
        for (int j = 0; j < 8; j++) h[j] = __float2half_rn(f[j]);
        *(uint4*)(g_xh + i) = *(const uint4*)h;
    } else {
        int idx = (blockIdx.x - XBLOCKS) * 256 + threadIdx.x;   // word index
        int n = idx >> 9;
        int w = idx & 511;
        unsigned word = ((const unsigned*)qw)[idx];
        int g = w >> 4;
        float s = sc[n * NGRP + g];
        float z = zp[n * NGRP + g];
        __half o[8];
#pragma unroll
        for (int i = 0; i < 8; i++) {
            float q = (float)((word >> (4 * i)) & 0xF);
            o[i] = __float2half_rn(s * (q - z));
        }
        *(uint4*)(g_wh + (size_t)n * KK + w * 8) = *(const uint4*)o;
    }
}

// ---------------- GEMM: 128 threads, 4 warps of 64x64 ----------------
__global__ void __launch_bounds__(128, 2)
gemm_fp16_kernel(const float* __restrict__ bias, float* __restrict__ out) {
    extern __shared__ __half sm[];
    const int tid = threadIdx.x;
    const int wid = tid >> 5;
    const int lane = tid & 31;
    const int warp_m = wid >> 1;       // 0..1 -> 64 rows
    const int warp_n = wid & 1;        // 0..1 -> 64 cols
    const int m0 = blockIdx.y * BM;
    const int n0 = blockIdx.x * BN;

    float acc[4][8][4];
#pragma unroll
    for (int i = 0; i < 4; i++)
#pragma unroll
        for (int j = 0; j < 8; j++)
#pragma unroll
            for (int r = 0; r < 4; r++) acc[i][j][r] = 0.f;

    // ---- loader constants (per thread; 128 threads) ----
    const int lrow = tid >> 3;         // 0..15
    const int lc = tid & 7;            // 0..7
    const uint32_t woff = (uint32_t)(lrow * PITCH + lc * 8) * 2;
    const __half* gA = g_xh + (size_t)(m0 + lrow) * KK + lc * 8;
    const __half* gB = g_wh + (size_t)(n0 + lrow) * KK + lc * 8;

    const uint32_t sbase = smem_u32(sm);
    const uint32_t stA0 = sbase;
    const uint32_t stA1 = sbase + STAGE_HALFS * 2;
    const uint32_t stA2 = sbase + STAGE_HALFS * 4;

    // piece i_: rows [i_*32, i_*32+32) of both tiles; 4 CP16 per thread
#define LOAD_PIECE(wb, i_)                                                    \
    do {                                                                      \
        uint32_t d0_ = (wb) + woff + (uint32_t)(i_ * 32 * PITCH * 2);         \
        uint32_t d1_ = d0_ + (uint32_t)(16 * PITCH * 2);                      \
        CP16(d0_, gA + (size_t)(i_ * 32) * KK);                               \
        CP16(d0_ + TILE_HALFS * 2, gB + (size_t)(i_ * 32) * KK);              \
        CP16(d1_, gA + (size_t)(i_ * 32 + 16) * KK);                          \
        CP16(d1_ + TILE_HALFS * 2, gB + (size_t)(i_ * 32 + 16) * KK);         \
    } while (0)

#define LOAD_STAGE_FULL(wb)                                                   \
    do {                                                                      \
        LOAD_PIECE(wb, 0); LOAD_PIECE(wb, 1);                                 \
        LOAD_PIECE(wb, 2); LOAD_PIECE(wb, 3);                                 \
        asm volatile("cp.async.commit_group;");                               \
        gA += BK; gB += BK;                                                   \
    } while (0)

    LOAD_STAGE_FULL(stA0);
    LOAD_STAGE_FULL(stA1);

    const int lrow16 = lane & 15;
    const int lk16 = (lane >> 4) * 16;
    const uint32_t a_ro = (uint32_t)((warp_m * 64 + lrow16) * PITCH) * 2 + lk16;
    const uint32_t b_ro = (uint32_t)((warp_n * 64 + lrow16) * PITCH) * 2 + lk16 + TILE_HALFS * 2;

    uint32_t ah[2][4][4], bb[2][4][4];

    // 8 MMAs for one (cur, mi) group: B groups bb[cur][0..3] cover 64 cols
#define MMA_GROUP(cur_, mi_)                                                  \
    do {                                                                      \
        _Pragma("unroll")                                                     \
        for (int nj_ = 0; nj_ < 8; nj_++) {                                   \
            uint32_t b0_ = bb[cur_][nj_ >> 1][nj_ & 1];                       \
            uint32_t b1_ = bb[cur_][nj_ >> 1][(nj_ & 1) + 2];                 \
            MMA16816(acc[mi_][nj_], ah[cur_][mi_], b0_, b1_);                 \
        }                                                                     \
    } while (0)

    // One stage; entry invariant: ks=0 frags already in buffers' slot 0.
#define STAGE_BODY(curb, nextb, loadb, do_load, pf_next, waitn)               \
    do {                                                                      \
        const uint32_t sA_ = (curb) + a_ro;                                   \
        const uint32_t sB_ = (curb) + b_ro;                                   \
        _Pragma("unroll")                                                     \
        for (int ks_ = 0; ks_ < 3; ks_++) {                                   \
            const int cur_ = ks_ & 1;                                         \
            const int nxt_ = cur_ ^ 1;                                        \
            const uint32_t kb_ = (uint32_t)((ks_ + 1) * 32);                  \
            LDSM_X4(ah[nxt_][0], sA_ + kb_);                                  \
            LDSM_X4(bb[nxt_][0], sB_ + kb_);                                  \
            MMA_GROUP(cur_, 0);                                               \
            LDSM_X4(ah[nxt_][1], sA_ + (uint32_t)(16 * PITCH * 2) + kb_);     \
            LDSM_X4(bb[nxt_][1], sB_ + (uint32_t)(16 * PITCH * 2) + kb_);     \
            MMA_GROUP(cur_, 1);                                               \
            LDSM_X4(ah[nxt_][2], sA_ + (uint32_t)(32 * PITCH * 2) + kb_);     \
            LDSM_X4(bb[nxt_][2], sB_ + (uint32_t)(32 * PITCH * 2) + kb_);     \
            if (do_load) LOAD_PIECE(loadb, ks_);                              \
            MMA_GROUP(cur_, 2);                                               \
            LDSM_X4(ah[nxt_][3], sA_ + (uint32_t)(48 * PITCH * 2) + kb_);     \
            LDSM_X4(bb[nxt_][3], sB_ + (uint32_t)(48 * PITCH * 2) + kb_);     \
            MMA_GROUP(cur_, 3);                                               \
        }                                                                     \
        if (do_load) {                                                        \
            LOAD_PIECE(loadb, 3);                                             \
            asm volatile("cp.async.commit_group;");                           \
            gA += BK; gB += BK;                                               \
        }                                                                     \
        asm volatile("cp.async.wait_group " #waitn ";" ::: "memory");         \
        __syncthreads();                                                      \
        if (pf_next) {                                                        \
            const uint32_t nA_ = (nextb) + a_ro;                              \
            const uint32_t nB_ = (nextb) + b_ro;                              \
            LDSM_X4(ah[0][0], nA_);                                           \
            LDSM_X4(bb[0][0], nB_);                                           \
            MMA_GROUP(1, 0);                                                  \
            LDSM_X4(ah[0][1], nA_ + (uint32_t)(16 * PITCH * 2));              \
            LDSM_X4(bb[0][1], nB_ + (uint32_t)(16 * PITCH * 2));              \
            MMA_GROUP(1, 1);                                                  \
            LDSM_X4(ah[0][2], nA_ + (uint32_t)(32 * PITCH * 2));              \
            LDSM_X4(bb[0][2], nB_ + (uint32_t)(32 * PITCH * 2));              \
            MMA_GROUP(1, 2);                                                  \
            LDSM_X4(ah[0][3], nA_ + (uint32_t)(48 * PITCH * 2));              \
            LDSM_X4(bb[0][3], nB_ + (uint32_t)(48 * PITCH * 2));              \
            MMA_GROUP(1, 3);                                                  \
        } else {                                                              \
            MMA_GROUP(1, 0); MMA_GROUP(1, 1);                                 \
            MMA_GROUP(1, 2); MMA_GROUP(1, 3);                                 \
        }                                                                     \
    } while (0)

    // prologue
    asm volatile("cp.async.wait_group 1;" ::: "memory");
    __syncthreads();
#pragma unroll
    for (int mi = 0; mi < 4; mi++)
        LDSM_X4(ah[0][mi], stA0 + a_ro + (uint32_t)(mi * 16 * PITCH * 2));
#pragma unroll
    for (int ng = 0; ng < 4; ng++)
        LDSM_X4(bb[0][ng], stA0 + b_ro + (uint32_t)(ng * 16 * PITCH * 2));

    for (int t = 0; t < 20; t++) {
        STAGE_BODY(stA0, stA1, stA2, true, true, 1);   // s = 3t
        STAGE_BODY(stA1, stA2, stA0, true, true, 1);   // s = 3t+1
        STAGE_BODY(stA2, stA0, stA1, true, true, 1);   // s = 3t+2
    }
    STAGE_BODY(stA0, stA1, stA2, true,  true, 1);      // s = 60
    STAGE_BODY(stA1, stA2, stA0, true,  true, 1);      // s = 61
    STAGE_BODY(stA2, stA0, stA1, false, true, 0);      // s = 62
    STAGE_BODY(stA0, stA1, stA2, false, false, 0);     // s = 63

    // ---------------- epilogue ----------------
    const int rb = lane >> 2;
    const int cb = (lane & 3) * 2;
#pragma unroll
    for (int mi = 0; mi < 4; mi++) {
        int m = m0 + warp_m * 64 + mi * 16 + rb;
#pragma unroll
        for (int nj = 0; nj < 8; nj++) {
            int n = n0 + warp_n * 64 + nj * 8 + cb;
            float2 bv = *(const float2*)(bias + n);
            float2 o0, o1;
            o0.x = acc[mi][nj][0] + bv.x;
            o0.y = acc[mi][nj][1] + bv.y;
            o1.x = acc[mi][nj][2] + bv.x;
            o1.y = acc[mi][nj][3] + bv.y;
            *(float2*)(out + (size_t)m * NN + n) = o0;
            *(float2*)(out + (size_t)(m + 8) * NN + n) = o1;
        }
    }
}

// ---------------- launch ----------------
extern "C" void kernel_launch(void* const* d_in, const int* in_sizes, int n_in,
                              void* d_out, int out_size) {
    const float* x    = (const float*)d_in[0];
    const int*   qw   = (const int*)d_in[1];
    const float* sc   = (const float*)d_in[2];
    const float* zp   = (const float*)d_in[3];
    const float* bias = (const float*)d_in[4];
    float* out = (float*)d_out;

    cudaFuncSetAttribute(gemm_fp16_kernel,
                         cudaFuncAttributeMaxDynamicSharedMemorySize, SMEM_BYTES);

    prep_kernel<<<XBLOCKS + (NN * KW) / 256, 256>>>(x, qw, sc, zp);
    gemm_fp16_kernel<<<dim3(NN / BN, MM / BM), 128, SMEM_BYTES>>>(bias, out);
}